// round 12
// baseline (speedup 1.0000x reference)
#include <cuda_runtime.h>
#include <cstdint>

// Problem constants
#define BB  4
#define SS  2048
#define DD  1024
#define HH  16
#define HDD 64
#define PFF 4096
#define NR  (BB * SS)   // 8192 rows

// ---------------------------------------------------------------------------
// Scratch (static __device__ — no allocation allowed)
// "tf32" buffers hold fp32 bit patterns pre-rounded with cvt.rna.tf32.
// ---------------------------------------------------------------------------
__device__ float g_q[BB * HH * SS * HDD];     // tf32 bits, [b][h][s][d]
__device__ float g_k[BB * HH * SS * HDD];     // tf32 bits
__device__ float g_v[BB * HH * SS * HDD];     // tf32 bits
__device__ float g_attn[NR * DD];             // tf32 bits
__device__ float g_tmp[NR * DD];              // fp32
__device__ float g_src1[NR * DD];             // fp32
__device__ float g_src1_t[NR * DD];           // tf32 bits
__device__ float g_src_t[NR * DD];            // tf32 bits
__device__ float g_ff1[NR * PFF];             // tf32 bits (ReLU applied)
__device__ float g_wt[12 * 1024 * 1024];      // tf32 bits: Wq|Wk|Wv|Wo|W1|W2

#define WT_WQ 0
#define WT_WK (1024 * 1024)
#define WT_WV (2 * 1024 * 1024)
#define WT_WO (3 * 1024 * 1024)
#define WT_W1 (4 * 1024 * 1024)
#define WT_W2 (8 * 1024 * 1024)

__device__ __forceinline__ uint32_t f2tf32(float x) {
    uint32_t y;
    asm("cvt.rna.tf32.f32 %0, %1;" : "=r"(y) : "f"(x));
    return y;
}

__device__ __forceinline__ void cp16(uint32_t dst_smem, const void* src) {
    asm volatile("cp.async.cg.shared.global [%0], [%1], 16;\n" ::
                 "r"(dst_smem), "l"(src));
}

__device__ __forceinline__ void mma_tf32(float& c0, float& c1, float& c2, float& c3,
                                         uint32_t a0, uint32_t a1, uint32_t a2, uint32_t a3,
                                         uint32_t b0, uint32_t b1) {
    asm volatile(
        "mma.sync.aligned.m16n8k8.row.col.f32.tf32.tf32.f32 "
        "{%0,%1,%2,%3}, {%4,%5,%6,%7}, {%8,%9}, {%0,%1,%2,%3};\n"
        : "+f"(c0), "+f"(c1), "+f"(c2), "+f"(c3)
        : "r"(a0), "r"(a1), "r"(a2), "r"(a3), "r"(b0), "r"(b1));
}

// ---------------------------------------------------------------------------
// Elementwise fp32 -> tf32-bits conversion (vectorized)
// ---------------------------------------------------------------------------
__global__ __launch_bounds__(256)
void cvt_tf32_kernel(const float4* __restrict__ in, uint4* __restrict__ out, int n4)
{
    const int i = blockIdx.x * blockDim.x + threadIdx.x;
    if (i < n4) {
        float4 v = in[i];
        uint4 o;
        o.x = f2tf32(v.x); o.y = f2tf32(v.y);
        o.z = f2tf32(v.z); o.w = f2tf32(v.w);
        out[i] = o;
    }
}

// ---------------------------------------------------------------------------
// TF32 tensor-core GEMM, pre-rounded operands (R9 configuration — known good).
// 128x128 block tile, BK=32; 128 threads = 4 warps in 2x2; warp tile 64x64.
// ---------------------------------------------------------------------------
#define BM 128
#define BN 128
#define BK 32
#define ASTRIDE 36
#define BSTRIDE 132
#define ASZ (BM * ASTRIDE)
#define BSZ (BK * BSTRIDE)
#define SMEM_FLOATS (2 * (ASZ + BSZ))

template <bool RELU, bool BHSD, bool CVT_OUT>
__global__ __launch_bounds__(128)
void mma_gemm_kernel(const float* __restrict__ A, const float* __restrict__ W,
                     const float* __restrict__ bias, float* __restrict__ C,
                     int M, int N, int K)
{
    extern __shared__ float sm[];
    float* sA[2] = { sm, sm + ASZ };
    float* sB[2] = { sm + 2 * ASZ, sm + 2 * ASZ + BSZ };

    const int tid  = threadIdx.x;
    const int lane = tid & 31;
    const int warp = tid >> 5;
    const int wm   = warp >> 1;   // 0..1
    const int wn   = warp & 1;    // 0..1
    const int bm   = blockIdx.y * BM;
    const int bn   = blockIdx.x * BN;

    const int a_row = tid >> 3;
    const int a_col = (tid & 7) * 4;
    const int b_row = tid >> 5;
    const int b_col = (tid & 31) * 4;

    const float* Ag = A + (size_t)(bm + a_row) * K + a_col;
    const float* Bg = W + (size_t)b_row * N + bn + b_col;

    uint32_t sA_dst[2], sB_dst[2];
    sA_dst[0] = (uint32_t)__cvta_generic_to_shared(sA[0] + a_row * ASTRIDE + a_col);
    sA_dst[1] = (uint32_t)__cvta_generic_to_shared(sA[1] + a_row * ASTRIDE + a_col);
    sB_dst[0] = (uint32_t)__cvta_generic_to_shared(sB[0] + b_row * BSTRIDE + b_col);
    sB_dst[1] = (uint32_t)__cvta_generic_to_shared(sB[1] + b_row * BSTRIDE + b_col);

    const int nk = K / BK;

    {
#pragma unroll
        for (int p = 0; p < 8; p++)
            cp16(sA_dst[0] + p * 16 * ASTRIDE * 4, Ag + (size_t)p * 16 * K);
#pragma unroll
        for (int p = 0; p < 8; p++)
            cp16(sB_dst[0] + p * 4 * BSTRIDE * 4, Bg + (size_t)p * 4 * N);
        asm volatile("cp.async.commit_group;\n" ::);
    }

    float acc[4][8][4];
#pragma unroll
    for (int i = 0; i < 4; i++)
#pragma unroll
        for (int j = 0; j < 8; j++)
#pragma unroll
            for (int r = 0; r < 4; r++) acc[i][j][r] = 0.0f;

    const int lr = lane >> 2;
    const int lc = lane & 3;

    int buf = 0;
    for (int t = 0; t < nk; ++t) {
        asm volatile("cp.async.wait_group 0;\n" ::);
        __syncthreads();

        if (t + 1 < nk) {
            const float* Agn = Ag + (size_t)(t + 1) * BK;
            const float* Bgn = Bg + (size_t)(t + 1) * BK * N;
            const int nb = buf ^ 1;
#pragma unroll
            for (int p = 0; p < 8; p++)
                cp16(sA_dst[nb] + p * 16 * ASTRIDE * 4, Agn + (size_t)p * 16 * K);
#pragma unroll
            for (int p = 0; p < 8; p++)
                cp16(sB_dst[nb] + p * 4 * BSTRIDE * 4, Bgn + (size_t)p * 4 * N);
            asm volatile("cp.async.commit_group;\n" ::);
        }

        const uint32_t* __restrict__ Au = (const uint32_t*)sA[buf];
        const uint32_t* __restrict__ Bu = (const uint32_t*)sB[buf];

#pragma unroll
        for (int kk = 0; kk < 4; ++kk) {
            const int k0 = kk * 8 + lc;
            uint32_t af[4][4];
#pragma unroll
            for (int mt = 0; mt < 4; mt++) {
                const int r0 = wm * 64 + mt * 16 + lr;
                af[mt][0] = Au[r0 * ASTRIDE + k0];
                af[mt][1] = Au[(r0 + 8) * ASTRIDE + k0];
                af[mt][2] = Au[r0 * ASTRIDE + k0 + 4];
                af[mt][3] = Au[(r0 + 8) * ASTRIDE + k0 + 4];
            }
            uint32_t bf[8][2];
#pragma unroll
            for (int nt = 0; nt < 8; nt++) {
                const int c0 = wn * 64 + nt * 8 + lr;
                bf[nt][0] = Bu[(kk * 8 + lc) * BSTRIDE + c0];
                bf[nt][1] = Bu[(kk * 8 + 4 + lc) * BSTRIDE + c0];
            }
#pragma unroll
            for (int mt = 0; mt < 4; mt++)
#pragma unroll
                for (int nt = 0; nt < 8; nt++)
                    mma_tf32(acc[mt][nt][0], acc[mt][nt][1],
                             acc[mt][nt][2], acc[mt][nt][3],
                             af[mt][0], af[mt][1], af[mt][2], af[mt][3],
                             bf[nt][0], bf[nt][1]);
        }
        buf ^= 1;
    }

#pragma unroll
    for (int mt = 0; mt < 4; mt++) {
#pragma unroll
        for (int nt = 0; nt < 8; nt++) {
            const int col = bn + wn * 64 + nt * 8 + lc * 2;
            const float bv0 = bias[col];
            const float bv1 = bias[col + 1];
#pragma unroll
            for (int half = 0; half < 2; half++) {
                const int row = bm + wm * 64 + mt * 16 + lr + half * 8;
                float v0 = acc[mt][nt][half * 2 + 0] + bv0;
                float v1 = acc[mt][nt][half * 2 + 1] + bv1;
                if (RELU) { v0 = fmaxf(v0, 0.0f); v1 = fmaxf(v1, 0.0f); }
                if (CVT_OUT) {
                    v0 = __uint_as_float(f2tf32(v0));
                    v1 = __uint_as_float(f2tf32(v1));
                }
                float* dst;
                if (BHSD) {
                    const int b_ = row >> 11;
                    const int s_ = row & 2047;
                    const int h_ = col >> 6;
                    const int d_ = col & 63;
                    dst = C + ((size_t)(b_ * HH + h_) * SS + s_) * HDD + d_;
                } else {
                    dst = C + (size_t)row * N + col;
                }
                *(float2*)dst = make_float2(v0, v1);
            }
        }
    }
}

// ---------------------------------------------------------------------------
// Flash attention, TF32 mma, cp.async DOUBLE-BUFFERED K/V.
// 128 threads = 4 warps; warp owns 16 query rows. Tile kt+1 K/V loads are in
// flight while tile kt computes. Compute order identical to R9.
// ---------------------------------------------------------------------------
#define KS_STRIDE 68
#define VS_STRIDE 72
#define PS_STRIDE 68
#define KV_STAGE_FLOATS (64 * KS_STRIDE + 64 * VS_STRIDE)
#define FLASH_SMEM_BYTES ((2 * KV_STAGE_FLOATS + 4 * 16 * PS_STRIDE) * 4)

__global__ __launch_bounds__(128)
void flash_mma_kernel(const float* __restrict__ Q, const float* __restrict__ Kg,
                      const float* __restrict__ Vg, float* __restrict__ Og)
{
    extern __shared__ float sm[];
    float* stage[2] = { sm, sm + KV_STAGE_FLOATS };        // [K | V] per stage
    float* Ps = sm + 2 * KV_STAGE_FLOATS;                  // 4 x [16][PS_STRIDE]

    const int tid  = threadIdx.x;
    const int warp = tid >> 5;
    const int lane = tid & 31;
    const int lr   = lane >> 2;
    const int lc   = lane & 3;
    const int bh   = blockIdx.y;
    const int q0   = blockIdx.x * 64;

    const float* qb = Q  + (size_t)bh * SS * HDD;
    const float* kb = Kg + (size_t)bh * SS * HDD;
    const float* vb = Vg + (size_t)bh * SS * HDD;

    uint32_t st_dstK[2], st_dstV[2];
    {
        const int row = tid >> 4;
        const int c4  = (tid & 15) << 2;
        st_dstK[0] = (uint32_t)__cvta_generic_to_shared(stage[0] + row * KS_STRIDE + c4);
        st_dstK[1] = (uint32_t)__cvta_generic_to_shared(stage[1] + row * KS_STRIDE + c4);
        st_dstV[0] = (uint32_t)__cvta_generic_to_shared(stage[0] + 64 * KS_STRIDE + row * VS_STRIDE + c4);
        st_dstV[1] = (uint32_t)__cvta_generic_to_shared(stage[1] + 64 * KS_STRIDE + row * VS_STRIDE + c4);
    }

    // issue K/V tile kt into stage s (8 float4 per operand per thread; rows
    // advance by 8 per pass -> smem byte step = 8*STRIDE*4)
    auto load_kv = [&](int kt, int s) {
        const float4* kp = (const float4*)(kb + (size_t)kt * 64 * HDD) + tid;
        const float4* vp = (const float4*)(vb + (size_t)kt * 64 * HDD) + tid;
#pragma unroll
        for (int p = 0; p < 8; p++) {
            cp16(st_dstK[s] + p * 8 * KS_STRIDE * 4, kp + p * 128);
            cp16(st_dstV[s] + p * 8 * VS_STRIDE * 4, vp + p * 128);
        }
        asm volatile("cp.async.commit_group;\n" ::);
    };

    // Q fragments (tf32 bits already; *2^-3 exact)
    uint32_t aq[8][4];
    {
        const int r0 = q0 + warp * 16 + lr;
#pragma unroll
        for (int kk = 0; kk < 8; kk++) {
            const int c = kk * 8 + lc;
            aq[kk][0] = __float_as_uint(qb[(size_t)r0 * HDD + c] * 0.125f);
            aq[kk][1] = __float_as_uint(qb[(size_t)(r0 + 8) * HDD + c] * 0.125f);
            aq[kk][2] = __float_as_uint(qb[(size_t)r0 * HDD + c + 4] * 0.125f);
            aq[kk][3] = __float_as_uint(qb[(size_t)(r0 + 8) * HDD + c + 4] * 0.125f);
        }
    }

    float o[8][4];
#pragma unroll
    for (int n = 0; n < 8; n++)
#pragma unroll
        for (int r = 0; r < 4; r++) o[n][r] = 0.0f;
    float m0 = -3.0e38f, m1 = -3.0e38f, l0 = 0.0f, l1 = 0.0f;

    float* Pw = Ps + warp * 16 * PS_STRIDE;

    load_kv(0, 0);   // prologue

    const int NT = SS / 64;
    for (int kt = 0; kt < NT; ++kt) {
        const int s = kt & 1;
        if (kt + 1 < NT) {
            load_kv(kt + 1, s ^ 1);
            asm volatile("cp.async.wait_group 1;\n" ::);
        } else {
            asm volatile("cp.async.wait_group 0;\n" ::);
        }
        __syncthreads();

        const uint32_t* Ku = (const uint32_t*)stage[s];
        const uint32_t* Vu = (const uint32_t*)(stage[s] + 64 * KS_STRIDE);

        // S = Q @ K^T
        float sc[8][4];
#pragma unroll
        for (int n = 0; n < 8; n++)
#pragma unroll
            for (int r = 0; r < 4; r++) sc[n][r] = 0.0f;

#pragma unroll
        for (int kk = 0; kk < 8; kk++) {
            const int kc = kk * 8 + lc;
#pragma unroll
            for (int n = 0; n < 8; n++) {
                const uint32_t b0 = Ku[(n * 8 + lr) * KS_STRIDE + kc];
                const uint32_t b1 = Ku[(n * 8 + lr) * KS_STRIDE + kc + 4];
                mma_tf32(sc[n][0], sc[n][1], sc[n][2], sc[n][3],
                         aq[kk][0], aq[kk][1], aq[kk][2], aq[kk][3], b0, b1);
            }
        }

        // online softmax
        float mx0 = -3.0e38f, mx1 = -3.0e38f;
#pragma unroll
        for (int n = 0; n < 8; n++) {
            mx0 = fmaxf(mx0, fmaxf(sc[n][0], sc[n][1]));
            mx1 = fmaxf(mx1, fmaxf(sc[n][2], sc[n][3]));
        }
        mx0 = fmaxf(mx0, __shfl_xor_sync(0xffffffffu, mx0, 1));
        mx0 = fmaxf(mx0, __shfl_xor_sync(0xffffffffu, mx0, 2));
        mx1 = fmaxf(mx1, __shfl_xor_sync(0xffffffffu, mx1, 1));
        mx1 = fmaxf(mx1, __shfl_xor_sync(0xffffffffu, mx1, 2));

        const float mn0 = fmaxf(m0, mx0);
        const float mn1 = fmaxf(m1, mx1);
        const float al0 = __expf(m0 - mn0);
        const float al1 = __expf(m1 - mn1);
        m0 = mn0; m1 = mn1;

        float rs0 = 0.0f, rs1 = 0.0f;
#pragma unroll
        for (int n = 0; n < 8; n++) {
            sc[n][0] = __expf(sc[n][0] - mn0);
            sc[n][1] = __expf(sc[n][1] - mn0);
            sc[n][2] = __expf(sc[n][2] - mn1);
            sc[n][3] = __expf(sc[n][3] - mn1);
            rs0 += sc[n][0] + sc[n][1];
            rs1 += sc[n][2] + sc[n][3];
        }
        rs0 += __shfl_xor_sync(0xffffffffu, rs0, 1);
        rs0 += __shfl_xor_sync(0xffffffffu, rs0, 2);
        rs1 += __shfl_xor_sync(0xffffffffu, rs1, 1);
        rs1 += __shfl_xor_sync(0xffffffffu, rs1, 2);
        l0 = l0 * al0 + rs0;
        l1 = l1 * al1 + rs1;

#pragma unroll
        for (int n = 0; n < 8; n++) {
            o[n][0] *= al0; o[n][1] *= al0;
            o[n][2] *= al1; o[n][3] *= al1;
        }

        // stage P (tf32 bits)
#pragma unroll
        for (int n = 0; n < 8; n++) {
            uint2 p01; p01.x = f2tf32(sc[n][0]); p01.y = f2tf32(sc[n][1]);
            *(uint2*)(Pw + lr * PS_STRIDE + n * 8 + 2 * lc) = p01;
            uint2 p23; p23.x = f2tf32(sc[n][2]); p23.y = f2tf32(sc[n][3]);
            *(uint2*)(Pw + (lr + 8) * PS_STRIDE + n * 8 + 2 * lc) = p23;
        }
        __syncwarp();

        // O += P @ V
        const uint32_t* Pu = (const uint32_t*)Pw;
#pragma unroll
        for (int kk = 0; kk < 8; kk++) {
            const int kc = kk * 8 + lc;
            const uint32_t a0 = Pu[lr * PS_STRIDE + kc];
            const uint32_t a1 = Pu[(lr + 8) * PS_STRIDE + kc];
            const uint32_t a2 = Pu[lr * PS_STRIDE + kc + 4];
            const uint32_t a3 = Pu[(lr + 8) * PS_STRIDE + kc + 4];
#pragma unroll
            for (int n = 0; n < 8; n++) {
                const uint32_t b0 = Vu[kc * VS_STRIDE + n * 8 + lr];
                const uint32_t b1 = Vu[(kc + 4) * VS_STRIDE + n * 8 + lr];
                mma_tf32(o[n][0], o[n][1], o[n][2], o[n][3],
                         a0, a1, a2, a3, b0, b1);
            }
        }
        __syncthreads();   // all warps done with stage s before it is refilled
    }

    // epilogue: normalize, round to tf32 bits (consumer: O-proj GEMM)
    const float inv0 = 1.0f / l0;
    const float inv1 = 1.0f / l1;
    const int b_ = bh >> 4;
    const int h_ = bh & 15;
    const size_t row0 = (size_t)b_ * SS + q0 + warp * 16 + lr;
    float* d0 = Og + row0 * DD + h_ * HDD;
    float* d1 = Og + (row0 + 8) * DD + h_ * HDD;
#pragma unroll
    for (int n = 0; n < 8; n++) {
        *(float2*)(d0 + n * 8 + 2 * lc) =
            make_float2(__uint_as_float(f2tf32(o[n][0] * inv0)),
                        __uint_as_float(f2tf32(o[n][1] * inv0)));
        *(float2*)(d1 + n * 8 + 2 * lc) =
            make_float2(__uint_as_float(f2tf32(o[n][2] * inv1)),
                        __uint_as_float(f2tf32(o[n][3] * inv1)));
    }
}

// ---------------------------------------------------------------------------
// Fused residual + LayerNorm. WRITE_T additionally writes a tf32-bits copy.
// ---------------------------------------------------------------------------
template <bool WRITE_T>
__global__ __launch_bounds__(256)
void ln_kernel(const float* __restrict__ x1, const float* __restrict__ x2,
               const float* __restrict__ gamma, const float* __restrict__ beta,
               float* __restrict__ out, float* __restrict__ out_t)
{
    const int row = blockIdx.x;
    const int tid = threadIdx.x;
    const float4 a = ((const float4*)(x1 + (size_t)row * DD))[tid];
    const float4 b = ((const float4*)(x2 + (size_t)row * DD))[tid];
    float4 x = make_float4(a.x + b.x, a.y + b.y, a.z + b.z, a.w + b.w);

    float s = x.x + x.y + x.z + x.w;
    float q = x.x * x.x + x.y * x.y + x.z * x.z + x.w * x.w;

    __shared__ float shs[8], shq[8];
    const int lane = tid & 31, wid = tid >> 5;
#pragma unroll
    for (int o = 16; o; o >>= 1) {
        s += __shfl_xor_sync(0xffffffffu, s, o);
        q += __shfl_xor_sync(0xffffffffu, q, o);
    }
    if (lane == 0) { shs[wid] = s; shq[wid] = q; }
    __syncthreads();
    if (tid == 0) {
        float ts = 0.0f, tq = 0.0f;
#pragma unroll
        for (int i = 0; i < 8; i++) { ts += shs[i]; tq += shq[i]; }
        shs[0] = ts; shq[0] = tq;
    }
    __syncthreads();
    const float mean = shs[0] * (1.0f / DD);
    const float var  = shq[0] * (1.0f / DD) - mean * mean;
    const float rstd = rsqrtf(var + 1e-5f);

    const float4 g  = ((const float4*)gamma)[tid];
    const float4 be = ((const float4*)beta)[tid];
    float4 o;
    o.x = (x.x - mean) * rstd * g.x + be.x;
    o.y = (x.y - mean) * rstd * g.y + be.y;
    o.z = (x.z - mean) * rstd * g.z + be.z;
    o.w = (x.w - mean) * rstd * g.w + be.w;
    ((float4*)(out + (size_t)row * DD))[tid] = o;
    if (WRITE_T) {
        float4 ot;
        ot.x = __uint_as_float(f2tf32(o.x));
        ot.y = __uint_as_float(f2tf32(o.y));
        ot.z = __uint_as_float(f2tf32(o.z));
        ot.w = __uint_as_float(f2tf32(o.w));
        ((float4*)(out_t + (size_t)row * DD))[tid] = ot;
    }
}

// ---------------------------------------------------------------------------
// Launch
// ---------------------------------------------------------------------------
extern "C" void kernel_launch(void* const* d_in, const int* in_sizes, int n_in,
                              void* d_out, int out_size)
{
    const float* src = (const float*)d_in[0];
    const float* Wq  = (const float*)d_in[1];
    const float* bq  = (const float*)d_in[2];
    const float* Wk  = (const float*)d_in[3];
    const float* bk  = (const float*)d_in[4];
    const float* Wv  = (const float*)d_in[5];
    const float* bv  = (const float*)d_in[6];
    const float* Wo  = (const float*)d_in[7];
    const float* bo  = (const float*)d_in[8];
    const float* g1  = (const float*)d_in[9];
    const float* b1  = (const float*)d_in[10];
    const float* W1  = (const float*)d_in[11];
    const float* bf1 = (const float*)d_in[12];
    const float* W2  = (const float*)d_in[13];
    const float* bf2 = (const float*)d_in[14];
    const float* g2  = (const float*)d_in[15];
    const float* b2  = (const float*)d_in[16];
    float* out = (float*)d_out;

    float *qp, *kp, *vp, *attnp, *tmpp, *src1p, *src1tp, *srctp, *ff1p, *wtp;
    cudaGetSymbolAddress((void**)&qp,     g_q);
    cudaGetSymbolAddress((void**)&kp,     g_k);
    cudaGetSymbolAddress((void**)&vp,     g_v);
    cudaGetSymbolAddress((void**)&attnp,  g_attn);
    cudaGetSymbolAddress((void**)&tmpp,   g_tmp);
    cudaGetSymbolAddress((void**)&src1p,  g_src1);
    cudaGetSymbolAddress((void**)&src1tp, g_src1_t);
    cudaGetSymbolAddress((void**)&srctp,  g_src_t);
    cudaGetSymbolAddress((void**)&ff1p,   g_ff1);
    cudaGetSymbolAddress((void**)&wtp,    g_wt);

    const int GEMM_SMEM = SMEM_FLOATS * 4;   // 70656 B

    cudaFuncSetAttribute(mma_gemm_kernel<false, true,  true>,
                         cudaFuncAttributeMaxDynamicSharedMemorySize, GEMM_SMEM);
    cudaFuncSetAttribute(mma_gemm_kernel<false, false, false>,
                         cudaFuncAttributeMaxDynamicSharedMemorySize, GEMM_SMEM);
    cudaFuncSetAttribute(mma_gemm_kernel<true,  false, true>,
                         cudaFuncAttributeMaxDynamicSharedMemorySize, GEMM_SMEM);
    cudaFuncSetAttribute(flash_mma_kernel,
                         cudaFuncAttributeMaxDynamicSharedMemorySize, FLASH_SMEM_BYTES);

    // Pre-round everything static to tf32 bits (src + 6 weight matrices)
    {
        const int T = 256;
        cvt_tf32_kernel<<<(NR * DD / 4 + T - 1) / T, T>>>(
            (const float4*)src, (uint4*)srctp, NR * DD / 4);
        cvt_tf32_kernel<<<(DD * DD / 4 + T - 1) / T, T>>>(
            (const float4*)Wq, (uint4*)(wtp + WT_WQ), DD * DD / 4);
        cvt_tf32_kernel<<<(DD * DD / 4 + T - 1) / T, T>>>(
            (const float4*)Wk, (uint4*)(wtp + WT_WK), DD * DD / 4);
        cvt_tf32_kernel<<<(DD * DD / 4 + T - 1) / T, T>>>(
            (const float4*)Wv, (uint4*)(wtp + WT_WV), DD * DD / 4);
        cvt_tf32_kernel<<<(DD * DD / 4 + T - 1) / T, T>>>(
            (const float4*)Wo, (uint4*)(wtp + WT_WO), DD * DD / 4);
        cvt_tf32_kernel<<<(DD * PFF / 4 + T - 1) / T, T>>>(
            (const float4*)W1, (uint4*)(wtp + WT_W1), DD * PFF / 4);
        cvt_tf32_kernel<<<(PFF * DD / 4 + T - 1) / T, T>>>(
            (const float4*)W2, (uint4*)(wtp + WT_W2), PFF * DD / 4);
    }

    dim3 gblk(128);
    dim3 gD(DD / BN, NR / BM);     // (8, 64)
    dim3 gPF(PFF / BN, NR / BM);   // (32, 64)
    dim3 gF(SS / 64, BB * HH);     // (32, 64)

    // QKV projections -> [B,H,S,HD], outputs tf32 bits
    mma_gemm_kernel<false, true, true><<<gD, gblk, GEMM_SMEM>>>(
        srctp, wtp + WT_WQ, bq, qp, NR, DD, DD);
    mma_gemm_kernel<false, true, true><<<gD, gblk, GEMM_SMEM>>>(
        srctp, wtp + WT_WK, bk, kp, NR, DD, DD);
    mma_gemm_kernel<false, true, true><<<gD, gblk, GEMM_SMEM>>>(
        srctp, wtp + WT_WV, bv, vp, NR, DD, DD);
    // attention (tensor-core flash, double-buffered)
    flash_mma_kernel<<<gF, dim3(128), FLASH_SMEM_BYTES>>>(qp, kp, vp, attnp);
    // O projection, outputs fp32
    mma_gemm_kernel<false, false, false><<<gD, gblk, GEMM_SMEM>>>(
        attnp, wtp + WT_WO, bo, tmpp, NR, DD, DD);
    // residual + LN 1 -> fp32 + tf32 copies
    ln_kernel<true><<<NR, dim3(256)>>>(src, tmpp, g1, b1, src1p, src1tp);
    // FFN1 (ReLU), outputs tf32 bits
    mma_gemm_kernel<true, false, true><<<gPF, gblk, GEMM_SMEM>>>(
        src1tp, wtp + WT_W1, bf1, ff1p, NR, PFF, DD);
    // FFN2, outputs fp32
    mma_gemm_kernel<false, false, false><<<gD, gblk, GEMM_SMEM>>>(
        ff1p, wtp + WT_W2, bf2, tmpp, NR, DD, PFF);
    // residual + LN 2 -> output
    ln_kernel<false><<<NR, dim3(256)>>>(src1p, tmpp, g2, b2, out, nullptr);
}

// round 14
// speedup vs baseline: 1.0593x; 1.0593x over previous
#include <cuda_runtime.h>
#include <cstdint>

// Problem constants
#define BB  4
#define SS  2048
#define DD  1024
#define HH  16
#define HDD 64
#define PFF 4096
#define NR  (BB * SS)   // 8192 rows

// ---------------------------------------------------------------------------
// Scratch (static __device__ — no allocation allowed)
// "tf32" buffers hold fp32 bit patterns pre-rounded with cvt.rna.tf32.
// ---------------------------------------------------------------------------
__device__ float g_q[BB * HH * SS * HDD];     // tf32 bits, [b][h][s][d]
__device__ float g_k[BB * HH * SS * HDD];     // tf32 bits
__device__ float g_v[BB * HH * SS * HDD];     // tf32 bits
__device__ float g_attn[NR * DD];             // tf32 bits
__device__ float g_tmp[NR * DD];              // fp32
__device__ float g_src1[NR * DD];             // fp32
__device__ float g_src1_t[NR * DD];           // tf32 bits
__device__ float g_src_t[NR * DD];            // tf32 bits
__device__ float g_ff1[NR * PFF];             // tf32 bits (ReLU applied)
__device__ float g_wt[12 * 1024 * 1024];      // tf32 bits: Wq|Wk|Wv|Wo|W1|W2

#define WT_WQ 0
#define WT_WK (1024 * 1024)
#define WT_WV (2 * 1024 * 1024)
#define WT_WO (3 * 1024 * 1024)
#define WT_W1 (4 * 1024 * 1024)
#define WT_W2 (8 * 1024 * 1024)

__device__ __forceinline__ uint32_t f2tf32(float x) {
    uint32_t y;
    asm("cvt.rna.tf32.f32 %0, %1;" : "=r"(y) : "f"(x));
    return y;
}

__device__ __forceinline__ void cp16(uint32_t dst_smem, const void* src) {
    asm volatile("cp.async.cg.shared.global [%0], [%1], 16;\n" ::
                 "r"(dst_smem), "l"(src));
}

__device__ __forceinline__ void mma_tf32(float& c0, float& c1, float& c2, float& c3,
                                         uint32_t a0, uint32_t a1, uint32_t a2, uint32_t a3,
                                         uint32_t b0, uint32_t b1) {
    asm volatile(
        "mma.sync.aligned.m16n8k8.row.col.f32.tf32.tf32.f32 "
        "{%0,%1,%2,%3}, {%4,%5,%6,%7}, {%8,%9}, {%0,%1,%2,%3};\n"
        : "+f"(c0), "+f"(c1), "+f"(c2), "+f"(c3)
        : "r"(a0), "r"(a1), "r"(a2), "r"(a3), "r"(b0), "r"(b1));
}

// ---------------------------------------------------------------------------
// Elementwise fp32 -> tf32-bits conversion (vectorized)
// ---------------------------------------------------------------------------
__global__ __launch_bounds__(256)
void cvt_tf32_kernel(const float4* __restrict__ in, uint4* __restrict__ out, int n4)
{
    const int i = blockIdx.x * blockDim.x + threadIdx.x;
    if (i < n4) {
        float4 v = in[i];
        uint4 o;
        o.x = f2tf32(v.x); o.y = f2tf32(v.y);
        o.z = f2tf32(v.z); o.w = f2tf32(v.w);
        out[i] = o;
    }
}

// ---------------------------------------------------------------------------
// TF32 tensor-core GEMM, pre-rounded operands (R9 configuration — known good).
// 128x128 block tile, BK=32; 128 threads = 4 warps in 2x2; warp tile 64x64.
// ---------------------------------------------------------------------------
#define BM 128
#define BN 128
#define BK 32
#define ASTRIDE 36
#define BSTRIDE 132
#define ASZ (BM * ASTRIDE)
#define BSZ (BK * BSTRIDE)
#define SMEM_FLOATS (2 * (ASZ + BSZ))

template <bool RELU, bool BHSD, bool CVT_OUT>
__global__ __launch_bounds__(128)
void mma_gemm_kernel(const float* __restrict__ A, const float* __restrict__ W,
                     const float* __restrict__ bias, float* __restrict__ C,
                     int M, int N, int K)
{
    extern __shared__ float sm[];
    float* sA[2] = { sm, sm + ASZ };
    float* sB[2] = { sm + 2 * ASZ, sm + 2 * ASZ + BSZ };

    const int tid  = threadIdx.x;
    const int lane = tid & 31;
    const int warp = tid >> 5;
    const int wm   = warp >> 1;   // 0..1
    const int wn   = warp & 1;    // 0..1
    const int bm   = blockIdx.y * BM;
    const int bn   = blockIdx.x * BN;

    const int a_row = tid >> 3;
    const int a_col = (tid & 7) * 4;
    const int b_row = tid >> 5;
    const int b_col = (tid & 31) * 4;

    const float* Ag = A + (size_t)(bm + a_row) * K + a_col;
    const float* Bg = W + (size_t)b_row * N + bn + b_col;

    uint32_t sA_dst[2], sB_dst[2];
    sA_dst[0] = (uint32_t)__cvta_generic_to_shared(sA[0] + a_row * ASTRIDE + a_col);
    sA_dst[1] = (uint32_t)__cvta_generic_to_shared(sA[1] + a_row * ASTRIDE + a_col);
    sB_dst[0] = (uint32_t)__cvta_generic_to_shared(sB[0] + b_row * BSTRIDE + b_col);
    sB_dst[1] = (uint32_t)__cvta_generic_to_shared(sB[1] + b_row * BSTRIDE + b_col);

    const int nk = K / BK;

    {
#pragma unroll
        for (int p = 0; p < 8; p++)
            cp16(sA_dst[0] + p * 16 * ASTRIDE * 4, Ag + (size_t)p * 16 * K);
#pragma unroll
        for (int p = 0; p < 8; p++)
            cp16(sB_dst[0] + p * 4 * BSTRIDE * 4, Bg + (size_t)p * 4 * N);
        asm volatile("cp.async.commit_group;\n" ::);
    }

    float acc[4][8][4];
#pragma unroll
    for (int i = 0; i < 4; i++)
#pragma unroll
        for (int j = 0; j < 8; j++)
#pragma unroll
            for (int r = 0; r < 4; r++) acc[i][j][r] = 0.0f;

    const int lr = lane >> 2;
    const int lc = lane & 3;

    int buf = 0;
    for (int t = 0; t < nk; ++t) {
        asm volatile("cp.async.wait_group 0;\n" ::);
        __syncthreads();

        if (t + 1 < nk) {
            const float* Agn = Ag + (size_t)(t + 1) * BK;
            const float* Bgn = Bg + (size_t)(t + 1) * BK * N;
            const int nb = buf ^ 1;
#pragma unroll
            for (int p = 0; p < 8; p++)
                cp16(sA_dst[nb] + p * 16 * ASTRIDE * 4, Agn + (size_t)p * 16 * K);
#pragma unroll
            for (int p = 0; p < 8; p++)
                cp16(sB_dst[nb] + p * 4 * BSTRIDE * 4, Bgn + (size_t)p * 4 * N);
            asm volatile("cp.async.commit_group;\n" ::);
        }

        const uint32_t* __restrict__ Au = (const uint32_t*)sA[buf];
        const uint32_t* __restrict__ Bu = (const uint32_t*)sB[buf];

#pragma unroll
        for (int kk = 0; kk < 4; ++kk) {
            const int k0 = kk * 8 + lc;
            uint32_t af[4][4];
#pragma unroll
            for (int mt = 0; mt < 4; mt++) {
                const int r0 = wm * 64 + mt * 16 + lr;
                af[mt][0] = Au[r0 * ASTRIDE + k0];
                af[mt][1] = Au[(r0 + 8) * ASTRIDE + k0];
                af[mt][2] = Au[r0 * ASTRIDE + k0 + 4];
                af[mt][3] = Au[(r0 + 8) * ASTRIDE + k0 + 4];
            }
            uint32_t bf[8][2];
#pragma unroll
            for (int nt = 0; nt < 8; nt++) {
                const int c0 = wn * 64 + nt * 8 + lr;
                bf[nt][0] = Bu[(kk * 8 + lc) * BSTRIDE + c0];
                bf[nt][1] = Bu[(kk * 8 + 4 + lc) * BSTRIDE + c0];
            }
#pragma unroll
            for (int mt = 0; mt < 4; mt++)
#pragma unroll
                for (int nt = 0; nt < 8; nt++)
                    mma_tf32(acc[mt][nt][0], acc[mt][nt][1],
                             acc[mt][nt][2], acc[mt][nt][3],
                             af[mt][0], af[mt][1], af[mt][2], af[mt][3],
                             bf[nt][0], bf[nt][1]);
        }
        buf ^= 1;
    }

#pragma unroll
    for (int mt = 0; mt < 4; mt++) {
#pragma unroll
        for (int nt = 0; nt < 8; nt++) {
            const int col = bn + wn * 64 + nt * 8 + lc * 2;
            const float bv0 = bias[col];
            const float bv1 = bias[col + 1];
#pragma unroll
            for (int half = 0; half < 2; half++) {
                const int row = bm + wm * 64 + mt * 16 + lr + half * 8;
                float v0 = acc[mt][nt][half * 2 + 0] + bv0;
                float v1 = acc[mt][nt][half * 2 + 1] + bv1;
                if (RELU) { v0 = fmaxf(v0, 0.0f); v1 = fmaxf(v1, 0.0f); }
                if (CVT_OUT) {
                    v0 = __uint_as_float(f2tf32(v0));
                    v1 = __uint_as_float(f2tf32(v1));
                }
                float* dst;
                if (BHSD) {
                    const int b_ = row >> 11;
                    const int s_ = row & 2047;
                    const int h_ = col >> 6;
                    const int d_ = col & 63;
                    dst = C + ((size_t)(b_ * HH + h_) * SS + s_) * HDD + d_;
                } else {
                    dst = C + (size_t)row * N + col;
                }
                *(float2*)dst = make_float2(v0, v1);
            }
        }
    }
}

// ---------------------------------------------------------------------------
// Flash attention, TF32 mma, K-only double buffer + single V buffer.
// smem = 2*K + V + P = 70656B -> 3 CTAs/SM retained (regs capped via
// __launch_bounds__(128,3)). Compute order identical to R9 (bit-identical out).
// cp.async queue: per iter push K[kt+1] (start) and V[kt+1] (end, after the
// post-PV barrier). start-wait: wg2 (last iter wg1) -> K[kt] done.
// pre-PV wait: wg1 (last iter wg0) -> V[kt] done. Both followed by barrier.
// ---------------------------------------------------------------------------
#define KS_STRIDE 68
#define VS_STRIDE 72
#define PS_STRIDE 68
#define K_BUF_FLOATS (64 * KS_STRIDE)
#define V_BUF_FLOATS (64 * VS_STRIDE)
#define FLASH_SMEM_BYTES ((2 * K_BUF_FLOATS + V_BUF_FLOATS + 4 * 16 * PS_STRIDE) * 4)

__global__ __launch_bounds__(128, 3)
void flash_mma_kernel(const float* __restrict__ Q, const float* __restrict__ Kg,
                      const float* __restrict__ Vg, float* __restrict__ Og)
{
    extern __shared__ float sm[];
    float* Kbuf[2] = { sm, sm + K_BUF_FLOATS };
    float* Vs = sm + 2 * K_BUF_FLOATS;
    float* Ps = Vs + V_BUF_FLOATS;

    const int tid  = threadIdx.x;
    const int warp = tid >> 5;
    const int lane = tid & 31;
    const int lr   = lane >> 2;
    const int lc   = lane & 3;
    const int bh   = blockIdx.y;
    const int q0   = blockIdx.x * 64;

    const float* qb = Q  + (size_t)bh * SS * HDD;
    const float* kb = Kg + (size_t)bh * SS * HDD;
    const float* vb = Vg + (size_t)bh * SS * HDD;

    // per-thread cp.async dst bases (row = tid>>4, c4 = (tid&15)*4)
    uint32_t dstK[2], dstV;
    {
        const int row = tid >> 4;
        const int c4  = (tid & 15) << 2;
        dstK[0] = (uint32_t)__cvta_generic_to_shared(Kbuf[0] + row * KS_STRIDE + c4);
        dstK[1] = (uint32_t)__cvta_generic_to_shared(Kbuf[1] + row * KS_STRIDE + c4);
        dstV    = (uint32_t)__cvta_generic_to_shared(Vs + row * VS_STRIDE + c4);
    }

    auto load_K = [&](int kt, int s) {
        const float4* kp = (const float4*)(kb + (size_t)kt * 64 * HDD) + tid;
#pragma unroll
        for (int p = 0; p < 8; p++)
            cp16(dstK[s] + p * 8 * KS_STRIDE * 4, kp + p * 128);
        asm volatile("cp.async.commit_group;\n" ::);
    };
    auto load_V = [&](int kt) {
        const float4* vp = (const float4*)(vb + (size_t)kt * 64 * HDD) + tid;
#pragma unroll
        for (int p = 0; p < 8; p++)
            cp16(dstV + p * 8 * VS_STRIDE * 4, vp + p * 128);
        asm volatile("cp.async.commit_group;\n" ::);
    };

    // Q fragments (tf32 bits already; *2^-3 exact)
    uint32_t aq[8][4];
    {
        const int r0 = q0 + warp * 16 + lr;
#pragma unroll
        for (int kk = 0; kk < 8; kk++) {
            const int c = kk * 8 + lc;
            aq[kk][0] = __float_as_uint(qb[(size_t)r0 * HDD + c] * 0.125f);
            aq[kk][1] = __float_as_uint(qb[(size_t)(r0 + 8) * HDD + c] * 0.125f);
            aq[kk][2] = __float_as_uint(qb[(size_t)r0 * HDD + c + 4] * 0.125f);
            aq[kk][3] = __float_as_uint(qb[(size_t)(r0 + 8) * HDD + c + 4] * 0.125f);
        }
    }

    float o[8][4];
#pragma unroll
    for (int n = 0; n < 8; n++)
#pragma unroll
        for (int r = 0; r < 4; r++) o[n][r] = 0.0f;
    float m0 = -3.0e38f, m1 = -3.0e38f, l0 = 0.0f, l1 = 0.0f;

    float* Pw = Ps + warp * 16 * PS_STRIDE;

    load_K(0, 0);   // group: K0
    load_V(0);      // group: V0

    const int NT = SS / 64;
    for (int kt = 0; kt < NT; ++kt) {
        const int s = kt & 1;
        const bool more = (kt + 1 < NT);
        if (more) load_K(kt + 1, s ^ 1);

        // K[kt] ready (queue newest: [V[kt], K[kt+1]] or [V[kt]])
        if (more) asm volatile("cp.async.wait_group 2;\n" ::);
        else      asm volatile("cp.async.wait_group 1;\n" ::);
        __syncthreads();

        const uint32_t* Ku = (const uint32_t*)Kbuf[s];

        // S = Q @ K^T
        float sc[8][4];
#pragma unroll
        for (int n = 0; n < 8; n++)
#pragma unroll
            for (int r = 0; r < 4; r++) sc[n][r] = 0.0f;

#pragma unroll
        for (int kk = 0; kk < 8; kk++) {
            const int kc = kk * 8 + lc;
#pragma unroll
            for (int n = 0; n < 8; n++) {
                const uint32_t b0 = Ku[(n * 8 + lr) * KS_STRIDE + kc];
                const uint32_t b1 = Ku[(n * 8 + lr) * KS_STRIDE + kc + 4];
                mma_tf32(sc[n][0], sc[n][1], sc[n][2], sc[n][3],
                         aq[kk][0], aq[kk][1], aq[kk][2], aq[kk][3], b0, b1);
            }
        }

        // online softmax
        float mx0 = -3.0e38f, mx1 = -3.0e38f;
#pragma unroll
        for (int n = 0; n < 8; n++) {
            mx0 = fmaxf(mx0, fmaxf(sc[n][0], sc[n][1]));
            mx1 = fmaxf(mx1, fmaxf(sc[n][2], sc[n][3]));
        }
        mx0 = fmaxf(mx0, __shfl_xor_sync(0xffffffffu, mx0, 1));
        mx0 = fmaxf(mx0, __shfl_xor_sync(0xffffffffu, mx0, 2));
        mx1 = fmaxf(mx1, __shfl_xor_sync(0xffffffffu, mx1, 1));
        mx1 = fmaxf(mx1, __shfl_xor_sync(0xffffffffu, mx1, 2));

        const float mn0 = fmaxf(m0, mx0);
        const float mn1 = fmaxf(m1, mx1);
        const float al0 = __expf(m0 - mn0);
        const float al1 = __expf(m1 - mn1);
        m0 = mn0; m1 = mn1;

        float rs0 = 0.0f, rs1 = 0.0f;
#pragma unroll
        for (int n = 0; n < 8; n++) {
            sc[n][0] = __expf(sc[n][0] - mn0);
            sc[n][1] = __expf(sc[n][1] - mn0);
            sc[n][2] = __expf(sc[n][2] - mn1);
            sc[n][3] = __expf(sc[n][3] - mn1);
            rs0 += sc[n][0] + sc[n][1];
            rs1 += sc[n][2] + sc[n][3];
        }
        rs0 += __shfl_xor_sync(0xffffffffu, rs0, 1);
        rs0 += __shfl_xor_sync(0xffffffffu, rs0, 2);
        rs1 += __shfl_xor_sync(0xffffffffu, rs1, 1);
        rs1 += __shfl_xor_sync(0xffffffffu, rs1, 2);
        l0 = l0 * al0 + rs0;
        l1 = l1 * al1 + rs1;

#pragma unroll
        for (int n = 0; n < 8; n++) {
            o[n][0] *= al0; o[n][1] *= al0;
            o[n][2] *= al1; o[n][3] *= al1;
        }

        // stage P (tf32 bits)
#pragma unroll
        for (int n = 0; n < 8; n++) {
            uint2 p01; p01.x = f2tf32(sc[n][0]); p01.y = f2tf32(sc[n][1]);
            *(uint2*)(Pw + lr * PS_STRIDE + n * 8 + 2 * lc) = p01;
            uint2 p23; p23.x = f2tf32(sc[n][2]); p23.y = f2tf32(sc[n][3]);
            *(uint2*)(Pw + (lr + 8) * PS_STRIDE + n * 8 + 2 * lc) = p23;
        }
        __syncwarp();

        // V[kt] ready (queue newest: [K[kt+1]] or [])
        if (more) asm volatile("cp.async.wait_group 1;\n" ::);
        else      asm volatile("cp.async.wait_group 0;\n" ::);
        __syncthreads();

        // O += P @ V
        const uint32_t* Pu = (const uint32_t*)Pw;
        const uint32_t* Vu = (const uint32_t*)Vs;
#pragma unroll
        for (int kk = 0; kk < 8; kk++) {
            const int kc = kk * 8 + lc;
            const uint32_t a0 = Pu[lr * PS_STRIDE + kc];
            const uint32_t a1 = Pu[(lr + 8) * PS_STRIDE + kc];
            const uint32_t a2 = Pu[lr * PS_STRIDE + kc + 4];
            const uint32_t a3 = Pu[(lr + 8) * PS_STRIDE + kc + 4];
#pragma unroll
            for (int n = 0; n < 8; n++) {
                const uint32_t b0 = Vu[kc * VS_STRIDE + n * 8 + lr];
                const uint32_t b1 = Vu[(kc + 4) * VS_STRIDE + n * 8 + lr];
                mma_tf32(o[n][0], o[n][1], o[n][2], o[n][3],
                         a0, a1, a2, a3, b0, b1);
            }
        }
        __syncthreads();   // all warps done with Vs (and Ps) before refill
        if (more) load_V(kt + 1);
    }

    // epilogue: normalize, round to tf32 bits (consumer: O-proj GEMM)
    const float inv0 = 1.0f / l0;
    const float inv1 = 1.0f / l1;
    const int b_ = bh >> 4;
    const int h_ = bh & 15;
    const size_t row0 = (size_t)b_ * SS + q0 + warp * 16 + lr;
    float* d0 = Og + row0 * DD + h_ * HDD;
    float* d1 = Og + (row0 + 8) * DD + h_ * HDD;
#pragma unroll
    for (int n = 0; n < 8; n++) {
        *(float2*)(d0 + n * 8 + 2 * lc) =
            make_float2(__uint_as_float(f2tf32(o[n][0] * inv0)),
                        __uint_as_float(f2tf32(o[n][1] * inv0)));
        *(float2*)(d1 + n * 8 + 2 * lc) =
            make_float2(__uint_as_float(f2tf32(o[n][2] * inv1)),
                        __uint_as_float(f2tf32(o[n][3] * inv1)));
    }
}

// ---------------------------------------------------------------------------
// Fused residual + LayerNorm. WRITE_T additionally writes a tf32-bits copy.
// ---------------------------------------------------------------------------
template <bool WRITE_T>
__global__ __launch_bounds__(256)
void ln_kernel(const float* __restrict__ x1, const float* __restrict__ x2,
               const float* __restrict__ gamma, const float* __restrict__ beta,
               float* __restrict__ out, float* __restrict__ out_t)
{
    const int row = blockIdx.x;
    const int tid = threadIdx.x;
    const float4 a = ((const float4*)(x1 + (size_t)row * DD))[tid];
    const float4 b = ((const float4*)(x2 + (size_t)row * DD))[tid];
    float4 x = make_float4(a.x + b.x, a.y + b.y, a.z + b.z, a.w + b.w);

    float s = x.x + x.y + x.z + x.w;
    float q = x.x * x.x + x.y * x.y + x.z * x.z + x.w * x.w;

    __shared__ float shs[8], shq[8];
    const int lane = tid & 31, wid = tid >> 5;
#pragma unroll
    for (int o = 16; o; o >>= 1) {
        s += __shfl_xor_sync(0xffffffffu, s, o);
        q += __shfl_xor_sync(0xffffffffu, q, o);
    }
    if (lane == 0) { shs[wid] = s; shq[wid] = q; }
    __syncthreads();
    if (tid == 0) {
        float ts = 0.0f, tq = 0.0f;
#pragma unroll
        for (int i = 0; i < 8; i++) { ts += shs[i]; tq += shq[i]; }
        shs[0] = ts; shq[0] = tq;
    }
    __syncthreads();
    const float mean = shs[0] * (1.0f / DD);
    const float var  = shq[0] * (1.0f / DD) - mean * mean;
    const float rstd = rsqrtf(var + 1e-5f);

    const float4 g  = ((const float4*)gamma)[tid];
    const float4 be = ((const float4*)beta)[tid];
    float4 o;
    o.x = (x.x - mean) * rstd * g.x + be.x;
    o.y = (x.y - mean) * rstd * g.y + be.y;
    o.z = (x.z - mean) * rstd * g.z + be.z;
    o.w = (x.w - mean) * rstd * g.w + be.w;
    ((float4*)(out + (size_t)row * DD))[tid] = o;
    if (WRITE_T) {
        float4 ot;
        ot.x = __uint_as_float(f2tf32(o.x));
        ot.y = __uint_as_float(f2tf32(o.y));
        ot.z = __uint_as_float(f2tf32(o.z));
        ot.w = __uint_as_float(f2tf32(o.w));
        ((float4*)(out_t + (size_t)row * DD))[tid] = ot;
    }
}

// ---------------------------------------------------------------------------
// Launch
// ---------------------------------------------------------------------------
extern "C" void kernel_launch(void* const* d_in, const int* in_sizes, int n_in,
                              void* d_out, int out_size)
{
    const float* src = (const float*)d_in[0];
    const float* Wq  = (const float*)d_in[1];
    const float* bq  = (const float*)d_in[2];
    const float* Wk  = (const float*)d_in[3];
    const float* bk  = (const float*)d_in[4];
    const float* Wv  = (const float*)d_in[5];
    const float* bv  = (const float*)d_in[6];
    const float* Wo  = (const float*)d_in[7];
    const float* bo  = (const float*)d_in[8];
    const float* g1  = (const float*)d_in[9];
    const float* b1  = (const float*)d_in[10];
    const float* W1  = (const float*)d_in[11];
    const float* bf1 = (const float*)d_in[12];
    const float* W2  = (const float*)d_in[13];
    const float* bf2 = (const float*)d_in[14];
    const float* g2  = (const float*)d_in[15];
    const float* b2  = (const float*)d_in[16];
    float* out = (float*)d_out;

    float *qp, *kp, *vp, *attnp, *tmpp, *src1p, *src1tp, *srctp, *ff1p, *wtp;
    cudaGetSymbolAddress((void**)&qp,     g_q);
    cudaGetSymbolAddress((void**)&kp,     g_k);
    cudaGetSymbolAddress((void**)&vp,     g_v);
    cudaGetSymbolAddress((void**)&attnp,  g_attn);
    cudaGetSymbolAddress((void**)&tmpp,   g_tmp);
    cudaGetSymbolAddress((void**)&src1p,  g_src1);
    cudaGetSymbolAddress((void**)&src1tp, g_src1_t);
    cudaGetSymbolAddress((void**)&srctp,  g_src_t);
    cudaGetSymbolAddress((void**)&ff1p,   g_ff1);
    cudaGetSymbolAddress((void**)&wtp,    g_wt);

    const int GEMM_SMEM = SMEM_FLOATS * 4;   // 70656 B

    cudaFuncSetAttribute(mma_gemm_kernel<false, true,  true>,
                         cudaFuncAttributeMaxDynamicSharedMemorySize, GEMM_SMEM);
    cudaFuncSetAttribute(mma_gemm_kernel<false, false, false>,
                         cudaFuncAttributeMaxDynamicSharedMemorySize, GEMM_SMEM);
    cudaFuncSetAttribute(mma_gemm_kernel<true,  false, true>,
                         cudaFuncAttributeMaxDynamicSharedMemorySize, GEMM_SMEM);
    cudaFuncSetAttribute(flash_mma_kernel,
                         cudaFuncAttributeMaxDynamicSharedMemorySize, FLASH_SMEM_BYTES);

    // Pre-round everything static to tf32 bits (src + 6 weight matrices)
    {
        const int T = 256;
        cvt_tf32_kernel<<<(NR * DD / 4 + T - 1) / T, T>>>(
            (const float4*)src, (uint4*)srctp, NR * DD / 4);
        cvt_tf32_kernel<<<(DD * DD / 4 + T - 1) / T, T>>>(
            (const float4*)Wq, (uint4*)(wtp + WT_WQ), DD * DD / 4);
        cvt_tf32_kernel<<<(DD * DD / 4 + T - 1) / T, T>>>(
            (const float4*)Wk, (uint4*)(wtp + WT_WK), DD * DD / 4);
        cvt_tf32_kernel<<<(DD * DD / 4 + T - 1) / T, T>>>(
            (const float4*)Wv, (uint4*)(wtp + WT_WV), DD * DD / 4);
        cvt_tf32_kernel<<<(DD * DD / 4 + T - 1) / T, T>>>(
            (const float4*)Wo, (uint4*)(wtp + WT_WO), DD * DD / 4);
        cvt_tf32_kernel<<<(DD * PFF / 4 + T - 1) / T, T>>>(
            (const float4*)W1, (uint4*)(wtp + WT_W1), DD * PFF / 4);
        cvt_tf32_kernel<<<(PFF * DD / 4 + T - 1) / T, T>>>(
            (const float4*)W2, (uint4*)(wtp + WT_W2), PFF * DD / 4);
    }

    dim3 gblk(128);
    dim3 gD(DD / BN, NR / BM);     // (8, 64)
    dim3 gPF(PFF / BN, NR / BM);   // (32, 64)
    dim3 gF(SS / 64, BB * HH);     // (32, 64)

    // QKV projections -> [B,H,S,HD], outputs tf32 bits
    mma_gemm_kernel<false, true, true><<<gD, gblk, GEMM_SMEM>>>(
        srctp, wtp + WT_WQ, bq, qp, NR, DD, DD);
    mma_gemm_kernel<false, true, true><<<gD, gblk, GEMM_SMEM>>>(
        srctp, wtp + WT_WK, bk, kp, NR, DD, DD);
    mma_gemm_kernel<false, true, true><<<gD, gblk, GEMM_SMEM>>>(
        srctp, wtp + WT_WV, bv, vp, NR, DD, DD);
    // attention (tensor-core flash, K-prefetch)
    flash_mma_kernel<<<gF, dim3(128), FLASH_SMEM_BYTES>>>(qp, kp, vp, attnp);
    // O projection, outputs fp32
    mma_gemm_kernel<false, false, false><<<gD, gblk, GEMM_SMEM>>>(
        attnp, wtp + WT_WO, bo, tmpp, NR, DD, DD);
    // residual + LN 1 -> fp32 + tf32 copies
    ln_kernel<true><<<NR, dim3(256)>>>(src, tmpp, g1, b1, src1p, src1tp);
    // FFN1 (ReLU), outputs tf32 bits
    mma_gemm_kernel<true, false, true><<<gPF, gblk, GEMM_SMEM>>>(
        src1tp, wtp + WT_W1, bf1, ff1p, NR, PFF, DD);
    // FFN2, outputs fp32
    mma_gemm_kernel<false, false, false><<<gD, gblk, GEMM_SMEM>>>(
        ff1p, wtp + WT_W2, bf2, tmpp, NR, DD, PFF);
    // residual + LN 2 -> output
    ln_kernel<false><<<NR, dim3(256)>>>(src1p, tmpp, g2, b2, out, nullptr);
}

// round 16
// speedup vs baseline: 1.3276x; 1.2532x over previous
#include <cuda_runtime.h>
#include <cuda_fp16.h>
#include <cstdint>

// Problem constants
#define BB  4
#define SS  2048
#define DD  1024
#define HH  16
#define HDD 64
#define PFF 4096
#define NR  (BB * SS)   // 8192 rows

// ---------------------------------------------------------------------------
// Scratch (static __device__ — no allocation allowed)
// ---------------------------------------------------------------------------
__device__ float  g_q[BB * HH * SS * HDD];     // tf32 bits (flash input)
__device__ float  g_k[BB * HH * SS * HDD];     // tf32 bits
__device__ float  g_v[BB * HH * SS * HDD];     // tf32 bits
__device__ float  g_tmp[NR * DD];              // fp32
__device__ float  g_src1[NR * DD];             // fp32
__device__ __half g_srch[NR * DD];             // half src (QKV GEMM A)
__device__ __half g_attnh[NR * DD];            // half attn out (O-proj A)
__device__ __half g_src1h[NR * DD];            // half LN1 out (FFN1 A)
__device__ __half g_ff1h[NR * PFF];            // half FFN1 out (FFN2 A)
__device__ __half g_wth[12 * 1024 * 1024];     // half weights, TRANSPOSED [N][K]

#define WT_WQ 0
#define WT_WK (1024 * 1024)
#define WT_WV (2 * 1024 * 1024)
#define WT_WO (3 * 1024 * 1024)
#define WT_W1 (4 * 1024 * 1024)
#define WT_W2 (8 * 1024 * 1024)

__device__ __forceinline__ uint32_t f2tf32(float x) {
    uint32_t y;
    asm("cvt.rna.tf32.f32 %0, %1;" : "=r"(y) : "f"(x));
    return y;
}

__device__ __forceinline__ void cp16(uint32_t dst_smem, const void* src) {
    asm volatile("cp.async.cg.shared.global [%0], [%1], 16;\n" ::
                 "r"(dst_smem), "l"(src));
}

__device__ __forceinline__ void mma_tf32(float& c0, float& c1, float& c2, float& c3,
                                         uint32_t a0, uint32_t a1, uint32_t a2, uint32_t a3,
                                         uint32_t b0, uint32_t b1) {
    asm volatile(
        "mma.sync.aligned.m16n8k8.row.col.f32.tf32.tf32.f32 "
        "{%0,%1,%2,%3}, {%4,%5,%6,%7}, {%8,%9}, {%0,%1,%2,%3};\n"
        : "+f"(c0), "+f"(c1), "+f"(c2), "+f"(c3)
        : "r"(a0), "r"(a1), "r"(a2), "r"(a3), "r"(b0), "r"(b1));
}

__device__ __forceinline__ void mma_f16(float& c0, float& c1, float& c2, float& c3,
                                        uint32_t a0, uint32_t a1, uint32_t a2, uint32_t a3,
                                        uint32_t b0, uint32_t b1) {
    asm volatile(
        "mma.sync.aligned.m16n8k16.row.col.f32.f16.f16.f32 "
        "{%0,%1,%2,%3}, {%4,%5,%6,%7}, {%8,%9}, {%0,%1,%2,%3};\n"
        : "+f"(c0), "+f"(c1), "+f"(c2), "+f"(c3)
        : "r"(a0), "r"(a1), "r"(a2), "r"(a3), "r"(b0), "r"(b1));
}

// ---------------------------------------------------------------------------
// src fp32 -> half (same layout)
// ---------------------------------------------------------------------------
__global__ __launch_bounds__(256)
void cvt_src_kernel(const float4* __restrict__ in, __half2* __restrict__ out, int n4)
{
    const int i = blockIdx.x * blockDim.x + threadIdx.x;
    if (i < n4) {
        float4 v = in[i];
        out[i * 2 + 0] = __floats2half2_rn(v.x, v.y);
        out[i * 2 + 1] = __floats2half2_rn(v.z, v.w);
    }
}

// ---------------------------------------------------------------------------
// All 6 weights: fp32 [K][N] -> half [N][K] (transpose + convert), one launch.
// grid (128,128,6); per-z bounds early-exit.
// ---------------------------------------------------------------------------
__global__ __launch_bounds__(256)
void w_cvt_kernel(const float* __restrict__ Wq, const float* __restrict__ Wk,
                  const float* __restrict__ Wv, const float* __restrict__ Wo,
                  const float* __restrict__ W1, const float* __restrict__ W2,
                  __half* __restrict__ dst)
{
    const int z = blockIdx.z;
    const float* src;
    size_t doff; int K, N;
    switch (z) {
        case 0: src = Wq; doff = WT_WQ; K = 1024; N = 1024; break;
        case 1: src = Wk; doff = WT_WK; K = 1024; N = 1024; break;
        case 2: src = Wv; doff = WT_WV; K = 1024; N = 1024; break;
        case 3: src = Wo; doff = WT_WO; K = 1024; N = 1024; break;
        case 4: src = W1; doff = WT_W1; K = 1024; N = 4096; break;
        default: src = W2; doff = WT_W2; K = 4096; N = 1024; break;
    }
    const int n0 = blockIdx.x * 32, k0 = blockIdx.y * 32;
    if (n0 >= N || k0 >= K) return;

    __shared__ float ts[32][33];
    const int tx = threadIdx.x & 31, ty = threadIdx.x >> 5;   // 32 x 8
#pragma unroll
    for (int i = 0; i < 32; i += 8)
        ts[ty + i][tx] = src[(size_t)(k0 + ty + i) * N + n0 + tx];
    __syncthreads();
    __half* out = dst + doff;
#pragma unroll
    for (int i = 0; i < 32; i += 8)
        out[(size_t)(n0 + ty + i) * K + k0 + tx] = __float2half_rn(ts[tx][ty + i]);
}

// ---------------------------------------------------------------------------
// FP16 tensor-core GEMM: C[M,N] = A[M,K] @ Bt[N,K]^T (+bias,+ReLU,+BHSD).
// 128x128 tile, BK=32 halves (2 k16 steps); 128 threads = 4 warps (2x2),
// warp tile 64x64. smem stride 40 halves (fragment-LDS conflict-free).
// OUTMODE: 0 = fp32, 1 = tf32-bits fp32 (flash input), 2 = half.
// ---------------------------------------------------------------------------
#define HSTR 40
#define HTILE (128 * HSTR)    // halves per operand buffer

template <bool RELU, bool BHSD, int OUTMODE>
__global__ __launch_bounds__(128)
void hgemm_kernel(const __half* __restrict__ A, const __half* __restrict__ Bt,
                  const float* __restrict__ bias, void* __restrict__ Cv,
                  int M, int N, int K)
{
    extern __shared__ __half smh[];
    __half* sA[2] = { smh, smh + HTILE };
    __half* sB[2] = { smh + 2 * HTILE, smh + 3 * HTILE };

    const int tid  = threadIdx.x;
    const int lane = tid & 31;
    const int warp = tid >> 5;
    const int wm   = warp >> 1;
    const int wn   = warp & 1;
    const int bm   = blockIdx.y * 128;
    const int bn   = blockIdx.x * 128;
    const int lr   = lane >> 2;
    const int lc   = lane & 3;

    // loader mapping: 128 threads, 16B (8 halves) each; 4 row-passes of 32
    const int l_row = tid >> 2;          // 0..31
    const int l_col = (tid & 3) * 8;     // halves

    const __half* Ag = A  + (size_t)(bm + l_row) * K + l_col;
    const __half* Bg = Bt + (size_t)(bn + l_row) * K + l_col;

    uint32_t sA_dst[2], sB_dst[2];
    sA_dst[0] = (uint32_t)__cvta_generic_to_shared(sA[0] + l_row * HSTR + l_col);
    sA_dst[1] = (uint32_t)__cvta_generic_to_shared(sA[1] + l_row * HSTR + l_col);
    sB_dst[0] = (uint32_t)__cvta_generic_to_shared(sB[0] + l_row * HSTR + l_col);
    sB_dst[1] = (uint32_t)__cvta_generic_to_shared(sB[1] + l_row * HSTR + l_col);

    const int nk = K >> 5;   // chunks of 32 halves

    {
#pragma unroll
        for (int p = 0; p < 4; p++) {
            cp16(sA_dst[0] + p * 32 * HSTR * 2, Ag + (size_t)p * 32 * K);
            cp16(sB_dst[0] + p * 32 * HSTR * 2, Bg + (size_t)p * 32 * K);
        }
        asm volatile("cp.async.commit_group;\n" ::);
    }

    float acc[4][8][4];
#pragma unroll
    for (int i = 0; i < 4; i++)
#pragma unroll
        for (int j = 0; j < 8; j++)
#pragma unroll
            for (int r = 0; r < 4; r++) acc[i][j][r] = 0.0f;

    int buf = 0;
    for (int t = 0; t < nk; ++t) {
        asm volatile("cp.async.wait_group 0;\n" ::);
        __syncthreads();

        if (t + 1 < nk) {
            const __half* Agn = Ag + (size_t)(t + 1) * 32;
            const __half* Bgn = Bg + (size_t)(t + 1) * 32;
            const int nb = buf ^ 1;
#pragma unroll
            for (int p = 0; p < 4; p++) {
                cp16(sA_dst[nb] + p * 32 * HSTR * 2, Agn + (size_t)p * 32 * K);
                cp16(sB_dst[nb] + p * 32 * HSTR * 2, Bgn + (size_t)p * 32 * K);
            }
            asm volatile("cp.async.commit_group;\n" ::);
        }

        const __half* __restrict__ Ah = sA[buf];
        const __half* __restrict__ Bh = sB[buf];

#pragma unroll
        for (int ks = 0; ks < 2; ++ks) {
            const int kb = ks * 16 + 2 * lc;
            uint32_t af[4][4];
#pragma unroll
            for (int mt = 0; mt < 4; mt++) {
                const int r0 = wm * 64 + mt * 16 + lr;
                af[mt][0] = *(const uint32_t*)&Ah[r0 * HSTR + kb];
                af[mt][1] = *(const uint32_t*)&Ah[(r0 + 8) * HSTR + kb];
                af[mt][2] = *(const uint32_t*)&Ah[r0 * HSTR + kb + 8];
                af[mt][3] = *(const uint32_t*)&Ah[(r0 + 8) * HSTR + kb + 8];
            }
            uint32_t bf[8][2];
#pragma unroll
            for (int nt = 0; nt < 8; nt++) {
                const int c0 = wn * 64 + nt * 8 + lr;
                bf[nt][0] = *(const uint32_t*)&Bh[c0 * HSTR + kb];
                bf[nt][1] = *(const uint32_t*)&Bh[c0 * HSTR + kb + 8];
            }
#pragma unroll
            for (int mt = 0; mt < 4; mt++)
#pragma unroll
                for (int nt = 0; nt < 8; nt++)
                    mma_f16(acc[mt][nt][0], acc[mt][nt][1],
                            acc[mt][nt][2], acc[mt][nt][3],
                            af[mt][0], af[mt][1], af[mt][2], af[mt][3],
                            bf[nt][0], bf[nt][1]);
        }
        buf ^= 1;
    }

#pragma unroll
    for (int mt = 0; mt < 4; mt++) {
#pragma unroll
        for (int nt = 0; nt < 8; nt++) {
            const int col = bn + wn * 64 + nt * 8 + lc * 2;
            const float bv0 = bias[col];
            const float bv1 = bias[col + 1];
#pragma unroll
            for (int half_ = 0; half_ < 2; half_++) {
                const int row = bm + wm * 64 + mt * 16 + lr + half_ * 8;
                float v0 = acc[mt][nt][half_ * 2 + 0] + bv0;
                float v1 = acc[mt][nt][half_ * 2 + 1] + bv1;
                if (RELU) { v0 = fmaxf(v0, 0.0f); v1 = fmaxf(v1, 0.0f); }
                if (OUTMODE == 2) {
                    __half2* dst = (__half2*)((__half*)Cv + (size_t)row * N + col);
                    *dst = __floats2half2_rn(v0, v1);
                } else {
                    if (OUTMODE == 1) {
                        v0 = __uint_as_float(f2tf32(v0));
                        v1 = __uint_as_float(f2tf32(v1));
                    }
                    float* dst;
                    if (BHSD) {
                        const int b_ = row >> 11;
                        const int s_ = row & 2047;
                        const int h_ = col >> 6;
                        const int d_ = col & 63;
                        dst = (float*)Cv + ((size_t)(b_ * HH + h_) * SS + s_) * HDD + d_;
                    } else {
                        dst = (float*)Cv + (size_t)row * N + col;
                    }
                    *(float2*)dst = make_float2(v0, v1);
                }
            }
        }
    }
}

// ---------------------------------------------------------------------------
// Flash attention, TF32 mma, K-prefetch (R14 — known good). Output -> half.
// ---------------------------------------------------------------------------
#define KS_STRIDE 68
#define VS_STRIDE 72
#define PS_STRIDE 68
#define K_BUF_FLOATS (64 * KS_STRIDE)
#define V_BUF_FLOATS (64 * VS_STRIDE)
#define FLASH_SMEM_BYTES ((2 * K_BUF_FLOATS + V_BUF_FLOATS + 4 * 16 * PS_STRIDE) * 4)

__global__ __launch_bounds__(128, 3)
void flash_mma_kernel(const float* __restrict__ Q, const float* __restrict__ Kg,
                      const float* __restrict__ Vg, __half* __restrict__ Og)
{
    extern __shared__ float sm[];
    float* Kbuf[2] = { sm, sm + K_BUF_FLOATS };
    float* Vs = sm + 2 * K_BUF_FLOATS;
    float* Ps = Vs + V_BUF_FLOATS;

    const int tid  = threadIdx.x;
    const int warp = tid >> 5;
    const int lane = tid & 31;
    const int lr   = lane >> 2;
    const int lc   = lane & 3;
    const int bh   = blockIdx.y;
    const int q0   = blockIdx.x * 64;

    const float* qb = Q  + (size_t)bh * SS * HDD;
    const float* kb = Kg + (size_t)bh * SS * HDD;
    const float* vb = Vg + (size_t)bh * SS * HDD;

    uint32_t dstK[2], dstV;
    {
        const int row = tid >> 4;
        const int c4  = (tid & 15) << 2;
        dstK[0] = (uint32_t)__cvta_generic_to_shared(Kbuf[0] + row * KS_STRIDE + c4);
        dstK[1] = (uint32_t)__cvta_generic_to_shared(Kbuf[1] + row * KS_STRIDE + c4);
        dstV    = (uint32_t)__cvta_generic_to_shared(Vs + row * VS_STRIDE + c4);
    }

    auto load_K = [&](int kt, int s) {
        const float4* kp = (const float4*)(kb + (size_t)kt * 64 * HDD) + tid;
#pragma unroll
        for (int p = 0; p < 8; p++)
            cp16(dstK[s] + p * 8 * KS_STRIDE * 4, kp + p * 128);
        asm volatile("cp.async.commit_group;\n" ::);
    };
    auto load_V = [&](int kt) {
        const float4* vp = (const float4*)(vb + (size_t)kt * 64 * HDD) + tid;
#pragma unroll
        for (int p = 0; p < 8; p++)
            cp16(dstV + p * 8 * VS_STRIDE * 4, vp + p * 128);
        asm volatile("cp.async.commit_group;\n" ::);
    };

    uint32_t aq[8][4];
    {
        const int r0 = q0 + warp * 16 + lr;
#pragma unroll
        for (int kk = 0; kk < 8; kk++) {
            const int c = kk * 8 + lc;
            aq[kk][0] = __float_as_uint(qb[(size_t)r0 * HDD + c] * 0.125f);
            aq[kk][1] = __float_as_uint(qb[(size_t)(r0 + 8) * HDD + c] * 0.125f);
            aq[kk][2] = __float_as_uint(qb[(size_t)r0 * HDD + c + 4] * 0.125f);
            aq[kk][3] = __float_as_uint(qb[(size_t)(r0 + 8) * HDD + c + 4] * 0.125f);
        }
    }

    float o[8][4];
#pragma unroll
    for (int n = 0; n < 8; n++)
#pragma unroll
        for (int r = 0; r < 4; r++) o[n][r] = 0.0f;
    float m0 = -3.0e38f, m1 = -3.0e38f, l0 = 0.0f, l1 = 0.0f;

    float* Pw = Ps + warp * 16 * PS_STRIDE;

    load_K(0, 0);
    load_V(0);

    const int NT = SS / 64;
    for (int kt = 0; kt < NT; ++kt) {
        const int s = kt & 1;
        const bool more = (kt + 1 < NT);
        if (more) load_K(kt + 1, s ^ 1);

        if (more) asm volatile("cp.async.wait_group 2;\n" ::);
        else      asm volatile("cp.async.wait_group 1;\n" ::);
        __syncthreads();

        const uint32_t* Ku = (const uint32_t*)Kbuf[s];

        float sc[8][4];
#pragma unroll
        for (int n = 0; n < 8; n++)
#pragma unroll
            for (int r = 0; r < 4; r++) sc[n][r] = 0.0f;

#pragma unroll
        for (int kk = 0; kk < 8; kk++) {
            const int kc = kk * 8 + lc;
#pragma unroll
            for (int n = 0; n < 8; n++) {
                const uint32_t b0 = Ku[(n * 8 + lr) * KS_STRIDE + kc];
                const uint32_t b1 = Ku[(n * 8 + lr) * KS_STRIDE + kc + 4];
                mma_tf32(sc[n][0], sc[n][1], sc[n][2], sc[n][3],
                         aq[kk][0], aq[kk][1], aq[kk][2], aq[kk][3], b0, b1);
            }
        }

        float mx0 = -3.0e38f, mx1 = -3.0e38f;
#pragma unroll
        for (int n = 0; n < 8; n++) {
            mx0 = fmaxf(mx0, fmaxf(sc[n][0], sc[n][1]));
            mx1 = fmaxf(mx1, fmaxf(sc[n][2], sc[n][3]));
        }
        mx0 = fmaxf(mx0, __shfl_xor_sync(0xffffffffu, mx0, 1));
        mx0 = fmaxf(mx0, __shfl_xor_sync(0xffffffffu, mx0, 2));
        mx1 = fmaxf(mx1, __shfl_xor_sync(0xffffffffu, mx1, 1));
        mx1 = fmaxf(mx1, __shfl_xor_sync(0xffffffffu, mx1, 2));

        const float mn0 = fmaxf(m0, mx0);
        const float mn1 = fmaxf(m1, mx1);
        const float al0 = __expf(m0 - mn0);
        const float al1 = __expf(m1 - mn1);
        m0 = mn0; m1 = mn1;

        float rs0 = 0.0f, rs1 = 0.0f;
#pragma unroll
        for (int n = 0; n < 8; n++) {
            sc[n][0] = __expf(sc[n][0] - mn0);
            sc[n][1] = __expf(sc[n][1] - mn0);
            sc[n][2] = __expf(sc[n][2] - mn1);
            sc[n][3] = __expf(sc[n][3] - mn1);
            rs0 += sc[n][0] + sc[n][1];
            rs1 += sc[n][2] + sc[n][3];
        }
        rs0 += __shfl_xor_sync(0xffffffffu, rs0, 1);
        rs0 += __shfl_xor_sync(0xffffffffu, rs0, 2);
        rs1 += __shfl_xor_sync(0xffffffffu, rs1, 1);
        rs1 += __shfl_xor_sync(0xffffffffu, rs1, 2);
        l0 = l0 * al0 + rs0;
        l1 = l1 * al1 + rs1;

#pragma unroll
        for (int n = 0; n < 8; n++) {
            o[n][0] *= al0; o[n][1] *= al0;
            o[n][2] *= al1; o[n][3] *= al1;
        }

#pragma unroll
        for (int n = 0; n < 8; n++) {
            uint2 p01; p01.x = f2tf32(sc[n][0]); p01.y = f2tf32(sc[n][1]);
            *(uint2*)(Pw + lr * PS_STRIDE + n * 8 + 2 * lc) = p01;
            uint2 p23; p23.x = f2tf32(sc[n][2]); p23.y = f2tf32(sc[n][3]);
            *(uint2*)(Pw + (lr + 8) * PS_STRIDE + n * 8 + 2 * lc) = p23;
        }
        __syncwarp();

        if (more) asm volatile("cp.async.wait_group 1;\n" ::);
        else      asm volatile("cp.async.wait_group 0;\n" ::);
        __syncthreads();

        const uint32_t* Pu = (const uint32_t*)Pw;
        const uint32_t* Vu = (const uint32_t*)Vs;
#pragma unroll
        for (int kk = 0; kk < 8; kk++) {
            const int kc = kk * 8 + lc;
            const uint32_t a0 = Pu[lr * PS_STRIDE + kc];
            const uint32_t a1 = Pu[(lr + 8) * PS_STRIDE + kc];
            const uint32_t a2 = Pu[lr * PS_STRIDE + kc + 4];
            const uint32_t a3 = Pu[(lr + 8) * PS_STRIDE + kc + 4];
#pragma unroll
            for (int n = 0; n < 8; n++) {
                const uint32_t b0 = Vu[kc * VS_STRIDE + n * 8 + lr];
                const uint32_t b1 = Vu[(kc + 4) * VS_STRIDE + n * 8 + lr];
                mma_tf32(o[n][0], o[n][1], o[n][2], o[n][3],
                         a0, a1, a2, a3, b0, b1);
            }
        }
        __syncthreads();
        if (more) load_V(kt + 1);
    }

    // epilogue: normalize, write HALF rows (consumer: fp16 O-proj GEMM)
    const float inv0 = 1.0f / l0;
    const float inv1 = 1.0f / l1;
    const int b_ = bh >> 4;
    const int h_ = bh & 15;
    const size_t row0 = (size_t)b_ * SS + q0 + warp * 16 + lr;
    __half* d0 = Og + row0 * DD + h_ * HDD;
    __half* d1 = Og + (row0 + 8) * DD + h_ * HDD;
#pragma unroll
    for (int n = 0; n < 8; n++) {
        *(__half2*)(d0 + n * 8 + 2 * lc) = __floats2half2_rn(o[n][0] * inv0, o[n][1] * inv0);
        *(__half2*)(d1 + n * 8 + 2 * lc) = __floats2half2_rn(o[n][2] * inv1, o[n][3] * inv1);
    }
}

// ---------------------------------------------------------------------------
// Fused residual + LayerNorm. WRITE_T writes a half copy for fp16 GEMMs.
// ---------------------------------------------------------------------------
template <bool WRITE_T>
__global__ __launch_bounds__(256)
void ln_kernel(const float* __restrict__ x1, const float* __restrict__ x2,
               const float* __restrict__ gamma, const float* __restrict__ beta,
               float* __restrict__ out, __half* __restrict__ out_t)
{
    const int row = blockIdx.x;
    const int tid = threadIdx.x;
    const float4 a = ((const float4*)(x1 + (size_t)row * DD))[tid];
    const float4 b = ((const float4*)(x2 + (size_t)row * DD))[tid];
    float4 x = make_float4(a.x + b.x, a.y + b.y, a.z + b.z, a.w + b.w);

    float s = x.x + x.y + x.z + x.w;
    float q = x.x * x.x + x.y * x.y + x.z * x.z + x.w * x.w;

    __shared__ float shs[8], shq[8];
    const int lane = tid & 31, wid = tid >> 5;
#pragma unroll
    for (int o = 16; o; o >>= 1) {
        s += __shfl_xor_sync(0xffffffffu, s, o);
        q += __shfl_xor_sync(0xffffffffu, q, o);
    }
    if (lane == 0) { shs[wid] = s; shq[wid] = q; }
    __syncthreads();
    if (tid == 0) {
        float ts = 0.0f, tq = 0.0f;
#pragma unroll
        for (int i = 0; i < 8; i++) { ts += shs[i]; tq += shq[i]; }
        shs[0] = ts; shq[0] = tq;
    }
    __syncthreads();
    const float mean = shs[0] * (1.0f / DD);
    const float var  = shq[0] * (1.0f / DD) - mean * mean;
    const float rstd = rsqrtf(var + 1e-5f);

    const float4 g  = ((const float4*)gamma)[tid];
    const float4 be = ((const float4*)beta)[tid];
    float4 o;
    o.x = (x.x - mean) * rstd * g.x + be.x;
    o.y = (x.y - mean) * rstd * g.y + be.y;
    o.z = (x.z - mean) * rstd * g.z + be.z;
    o.w = (x.w - mean) * rstd * g.w + be.w;
    ((float4*)(out + (size_t)row * DD))[tid] = o;
    if (WRITE_T) {
        __half2* p = (__half2*)(out_t + (size_t)row * DD + tid * 4);
        p[0] = __floats2half2_rn(o.x, o.y);
        p[1] = __floats2half2_rn(o.z, o.w);
    }
}

// ---------------------------------------------------------------------------
// Launch
// ---------------------------------------------------------------------------
extern "C" void kernel_launch(void* const* d_in, const int* in_sizes, int n_in,
                              void* d_out, int out_size)
{
    const float* src = (const float*)d_in[0];
    const float* Wq  = (const float*)d_in[1];
    const float* bq  = (const float*)d_in[2];
    const float* Wk  = (const float*)d_in[3];
    const float* bk  = (const float*)d_in[4];
    const float* Wv  = (const float*)d_in[5];
    const float* bv  = (const float*)d_in[6];
    const float* Wo  = (const float*)d_in[7];
    const float* bo  = (const float*)d_in[8];
    const float* g1  = (const float*)d_in[9];
    const float* b1  = (const float*)d_in[10];
    const float* W1  = (const float*)d_in[11];
    const float* bf1 = (const float*)d_in[12];
    const float* W2  = (const float*)d_in[13];
    const float* bf2 = (const float*)d_in[14];
    const float* g2  = (const float*)d_in[15];
    const float* b2  = (const float*)d_in[16];
    float* out = (float*)d_out;

    float *qp, *kp, *vp, *tmpp, *src1p;
    __half *srchp, *attnhp, *src1hp, *ff1hp, *wthp;
    cudaGetSymbolAddress((void**)&qp,     g_q);
    cudaGetSymbolAddress((void**)&kp,     g_k);
    cudaGetSymbolAddress((void**)&vp,     g_v);
    cudaGetSymbolAddress((void**)&tmpp,   g_tmp);
    cudaGetSymbolAddress((void**)&src1p,  g_src1);
    cudaGetSymbolAddress((void**)&srchp,  g_srch);
    cudaGetSymbolAddress((void**)&attnhp, g_attnh);
    cudaGetSymbolAddress((void**)&src1hp, g_src1h);
    cudaGetSymbolAddress((void**)&ff1hp,  g_ff1h);
    cudaGetSymbolAddress((void**)&wthp,   g_wth);

    const int HGEMM_SMEM = 4 * HTILE * 2;   // 40960 B

    cudaFuncSetAttribute(hgemm_kernel<false, true,  1>,
                         cudaFuncAttributeMaxDynamicSharedMemorySize, HGEMM_SMEM);
    cudaFuncSetAttribute(hgemm_kernel<false, false, 0>,
                         cudaFuncAttributeMaxDynamicSharedMemorySize, HGEMM_SMEM);
    cudaFuncSetAttribute(hgemm_kernel<true,  false, 2>,
                         cudaFuncAttributeMaxDynamicSharedMemorySize, HGEMM_SMEM);
    cudaFuncSetAttribute(flash_mma_kernel,
                         cudaFuncAttributeMaxDynamicSharedMemorySize, FLASH_SMEM_BYTES);

    // #0: src fp32 -> half ; #1: all weights transpose+cvt (one launch)
    cvt_src_kernel<<<(NR * DD / 4 + 255) / 256, 256>>>(
        (const float4*)src, (__half2*)srchp, NR * DD / 4);
    w_cvt_kernel<<<dim3(128, 128, 6), 256>>>(Wq, Wk, Wv, Wo, W1, W2, wthp);

    dim3 gblk(128);
    dim3 gD(DD / 128, NR / 128);     // (8, 64)
    dim3 gPF(PFF / 128, NR / 128);   // (32, 64)
    dim3 gF(SS / 64, BB * HH);       // (32, 64)

    // #2-4: QKV projections -> [B,H,S,HD] tf32-bits fp32 (flash input)
    hgemm_kernel<false, true, 1><<<gD, gblk, HGEMM_SMEM>>>(
        srchp, wthp + WT_WQ, bq, qp, NR, DD, DD);
    hgemm_kernel<false, true, 1><<<gD, gblk, HGEMM_SMEM>>>(
        srchp, wthp + WT_WK, bk, kp, NR, DD, DD);
    hgemm_kernel<false, true, 1><<<gD, gblk, HGEMM_SMEM>>>(
        srchp, wthp + WT_WV, bv, vp, NR, DD, DD);
    // #5: attention (tf32 flash), outputs half
    flash_mma_kernel<<<gF, dim3(128), FLASH_SMEM_BYTES>>>(qp, kp, vp, attnhp);
    // #6: O projection (fp16), outputs fp32
    hgemm_kernel<false, false, 0><<<gD, gblk, HGEMM_SMEM>>>(
        attnhp, wthp + WT_WO, bo, tmpp, NR, DD, DD);
    // #7: residual + LN 1 -> fp32 + half
    ln_kernel<true><<<NR, dim3(256)>>>(src, tmpp, g1, b1, src1p, src1hp);
    // #8: FFN1 (ReLU), outputs half
    hgemm_kernel<true, false, 2><<<gPF, gblk, HGEMM_SMEM>>>(
        src1hp, wthp + WT_W1, bf1, ff1hp, NR, PFF, DD);
    // #9: FFN2, outputs fp32
    hgemm_kernel<false, false, 0><<<gD, gblk, HGEMM_SMEM>>>(
        ff1hp, wthp + WT_W2, bf2, tmpp, NR, DD, PFF);
    // #10: residual + LN 2 -> output
    ln_kernel<false><<<NR, dim3(256)>>>(src1p, tmpp, g2, b2, out, nullptr);
}